// round 2
// baseline (speedup 1.0000x reference)
#include <cuda_runtime.h>
#include <math.h>

#define BATCH 1024
#define SEQ   200
#define EMB   128
#define NHEAD 8
#define TSTEPS 199
#define PW    640      // columns of precomputed P: [K(128) | V(128) | KP(128) | Q2(128) | Q3(128)]
#define KST   132      // K shared row stride (per s), padded
#define VST   204      // V-transposed shared row stride (per e), padded
#define NEGF  (-3.402823466e38f)

// ---------------- device scratch (static allocation is allowed) ----------------
__device__ float g_P[(size_t)BATCH * SEQ * PW];   // 524 MB precomputed projections
__device__ float g_Wcat[EMB * PW];                // [k][640] combined weight matrix
__device__ float g_qhat[BATCH * EMB];             // h_hat @ Wq1
__device__ float g_qvec[2 * EMB];                 // vl@Wq2, vf@Wq3

// ---------------- build combined weights: [Wk | Wv | Wp@Wo^T | Wq2 | Wq3] -------
__global__ void wcat_kernel(const float* __restrict__ Wk, const float* __restrict__ Wv,
                            const float* __restrict__ Wo, const float* __restrict__ Wp,
                            const float* __restrict__ Wq) {
    int e = threadIdx.x;          // k-index (0..127)
    int c = blockIdx.x;           // output column (0..639)
    float v;
    if (c < 128) {
        v = Wk[e * 128 + c];
    } else if (c < 256) {
        v = Wv[e * 128 + (c - 128)];
    } else if (c < 384) {
        int i = c - 256;          // Wpo[e][i] = sum_j Wp[e][j] * Wo[i][j]
        float s = 0.f;
        for (int j = 0; j < 128; j++) s += Wp[e * 128 + j] * Wo[i * 128 + j];
        v = s;
    } else if (c < 512) {
        v = Wq[(128 + e) * 128 + (c - 384)];   // Wq2
    } else {
        v = Wq[(256 + e) * 128 + (c - 512)];   // Wq3
    }
    g_Wcat[e * PW + c] = v;
}

// ---------------- h_hat mean + qhat = h_hat @ Wq1 (+ broadcast vectors) ---------
__global__ void prep_kernel(const float* __restrict__ enc, const float* __restrict__ vl,
                            const float* __restrict__ vf, const float* __restrict__ Wq) {
    __shared__ float hh[EMB];
    int b = blockIdx.x, e = threadIdx.x;
    const float* p = enc + (size_t)b * SEQ * EMB + e;
    float s = 0.f;
    for (int i = 0; i < SEQ; i++) s += p[(size_t)i * EMB];
    hh[e] = s * (1.0f / (float)SEQ);
    __syncthreads();
    float q = 0.f;
    for (int k = 0; k < 128; k++) q += hh[k] * Wq[k * 128 + e];
    g_qhat[b * EMB + e] = q;
    if (b == 0) {
        float a = 0.f, c = 0.f;
        for (int k = 0; k < 128; k++) {
            a += vl[k] * Wq[(128 + k) * 128 + e];
            c += vf[k] * Wq[(256 + k) * 128 + e];
        }
        g_qvec[e] = a;
        g_qvec[128 + e] = c;
    }
}

// ---------------- SGEMM: g_P[204800,640] = enc[204800,128] @ g_Wcat[128,640] ----
__global__ __launch_bounds__(256, 1) void gemm_kernel(const float* __restrict__ A) {
    extern __shared__ float smg[];
    float* As = smg;               // transposed tile: As[k*132 + m], 128x128
    float* Bs = smg + 128 * 132;   // Bs[k*128 + n]
    int m0 = blockIdx.x * 128, n0 = blockIdx.y * 128;
    int tid = threadIdx.x;
    for (int it = 0; it < 64; it++) {
        int idx = tid + it * 256;
        int k = idx & 127, m = idx >> 7;
        As[k * 132 + m] = A[(size_t)(m0 + m) * 128 + k];
        Bs[m * 128 + k] = g_Wcat[m * PW + n0 + k];   // here m=row(k-dim), k=col(n-dim)
    }
    __syncthreads();
    int tx = tid & 15, ty = tid >> 4;
    float acc[8][8];
#pragma unroll
    for (int i = 0; i < 8; i++)
#pragma unroll
        for (int j = 0; j < 8; j++) acc[i][j] = 0.f;
#pragma unroll 4
    for (int k = 0; k < 128; k++) {
        float4 a0 = *(float4*)&As[k * 132 + ty * 8];
        float4 a1 = *(float4*)&As[k * 132 + ty * 8 + 4];
        float4 b0 = *(float4*)&Bs[k * 128 + tx * 8];
        float4 b1 = *(float4*)&Bs[k * 128 + tx * 8 + 4];
        float av[8] = {a0.x, a0.y, a0.z, a0.w, a1.x, a1.y, a1.z, a1.w};
        float bv[8] = {b0.x, b0.y, b0.z, b0.w, b1.x, b1.y, b1.z, b1.w};
#pragma unroll
        for (int i = 0; i < 8; i++)
#pragma unroll
            for (int j = 0; j < 8; j++) acc[i][j] += av[i] * bv[j];
    }
#pragma unroll
    for (int i = 0; i < 8; i++) {
        float* cr = &g_P[(size_t)(m0 + ty * 8 + i) * PW + n0 + tx * 8];
        *(float4*)cr       = make_float4(acc[i][0], acc[i][1], acc[i][2], acc[i][3]);
        *(float4*)(cr + 4) = make_float4(acc[i][4], acc[i][5], acc[i][6], acc[i][7]);
    }
}

// ---------------- persistent per-batch greedy decode (199 steps) ----------------
__global__ __launch_bounds__(256, 1) void decode_kernel(float* __restrict__ outLogits,
                                                        float* __restrict__ outLogp,
                                                        float* __restrict__ outSol) {
    extern __shared__ float sm[];
    float*    Ksh   = sm;                          // 200*132
    float*    Vt    = Ksh + SEQ * KST;             // 128*204 (V transposed: Vt[e*VST+s])
    float*    attn  = Vt + EMB * VST;              // 8*200
    float*    qv    = attn + NHEAD * SEQ;          // 128
    float*    ctx   = qv + EMB;                    // 128
    float*    ush   = ctx + EMB;                   // 200
    float*    redv  = ush + SEQ;                   // 8
    float*    reds  = redv + 8;                    // 8
    int*      redi  = (int*)(reds + 8);            // 8
    unsigned* maskw = (unsigned*)(redi + 8);       // 8
    int*      sols  = (int*)(maskw + 8);           // 200
    float*    s_logp = (float*)(sols + SEQ);
    int*      s_ints = (int*)(s_logp + 1);         // [0]=idx_prev [1]=idx0 [2]=best_idx
    float*    s_bmax = (float*)(s_ints + 3);

    int b = blockIdx.x;
    int tid = threadIdx.x, lane = tid & 31, w = tid >> 5;
    size_t rowb = (size_t)b * SEQ;
    const float* __restrict__ Pb = g_P + rowb * PW;

    // load K and V (transposed) into SMEM
    for (int i = tid; i < SEQ * EMB; i += 256) {
        int s = i >> 7, e = i & 127;
        Ksh[s * KST + e] = Pb[(size_t)s * PW + e];
        Vt[e * VST + s]  = Pb[(size_t)s * PW + 128 + e];
    }
    if (tid < 8) maskw[tid] = (tid == 0) ? 1u : 0u;   // depot (s=0) pre-masked
    if (tid == 0) { *s_logp = 0.f; sols[0] = 0; s_ints[0] = 0; s_ints[1] = 0; }
    __syncthreads();

    const float inv_scale = 0.08838834764831845f;    // 1/sqrt(128)

    for (int t = 0; t < TSTEPS; t++) {
        // ---- Phase Q: q = qhat + q_last + q_first, pre-scaled by 1/sqrt(dh) ----
        if (tid < 128) {
            float q = g_qhat[b * EMB + tid];
            if (t == 0) {
                q += g_qvec[tid] + g_qvec[128 + tid];
            } else {
                q += Pb[(size_t)s_ints[0] * PW + 384 + tid]    // Q2[b, idx_prev]
                   + Pb[(size_t)s_ints[1] * PW + 512 + tid];   // Q3[b, idx0]
            }
            qv[tid] = q * 0.25f;
        }
        __syncthreads();

        // ---- Phase S: warp h computes masked scores + softmax for its head ----
        {
            int h = w;
            const float4* qp = (const float4*)&qv[h << 4];
            float4 q0 = qp[0], q1 = qp[1], q2 = qp[2], q3 = qp[3];
            float sc[7];
#pragma unroll
            for (int r = 0; r < 7; r++) {
                int s = lane + (r << 5);
                float v = NEGF;
                if (s < SEQ && !((maskw[s >> 5] >> (s & 31)) & 1u)) {
                    const float4* kr = (const float4*)&Ksh[s * KST + (h << 4)];
                    float4 k0 = kr[0], k1 = kr[1], k2 = kr[2], k3 = kr[3];
                    v  = q0.x * k0.x + q0.y * k0.y + q0.z * k0.z + q0.w * k0.w;
                    v += q1.x * k1.x + q1.y * k1.y + q1.z * k1.z + q1.w * k1.w;
                    v += q2.x * k2.x + q2.y * k2.y + q2.z * k2.z + q2.w * k2.w;
                    v += q3.x * k3.x + q3.y * k3.y + q3.z * k3.z + q3.w * k3.w;
                }
                sc[r] = v;
            }
            float mx = sc[0];
#pragma unroll
            for (int r = 1; r < 7; r++) mx = fmaxf(mx, sc[r]);
#pragma unroll
            for (int o = 16; o; o >>= 1) mx = fmaxf(mx, __shfl_xor_sync(0xffffffffu, mx, o));
            float er[7], ssum = 0.f;
#pragma unroll
            for (int r = 0; r < 7; r++) { er[r] = expf(sc[r] - mx); ssum += er[r]; }
#pragma unroll
            for (int o = 16; o; o >>= 1) ssum += __shfl_xor_sync(0xffffffffu, ssum, o);
            float inv = 1.f / ssum;
#pragma unroll
            for (int r = 0; r < 7; r++) {
                int s = lane + (r << 5);
                if (s < SEQ) attn[h * SEQ + s] = er[r] * inv;
            }
        }
        __syncthreads();

        // ---- Phase C: ctx[c] = sum_s attn[h(c)][s] * V[s][c] ----
        if (tid < 128) {
            int c = tid, h = c >> 4;
            const float* ar = &attn[h * SEQ];
            const float* vr = &Vt[c * VST];
            float acc = 0.f;
#pragma unroll 5
            for (int s4 = 0; s4 < SEQ / 4; s4++) {
                float4 a  = *(const float4*)&ar[s4 * 4];
                float4 vv = *(const float4*)&vr[s4 * 4];
                acc += a.x * vv.x + a.y * vv.y + a.z * vv.z + a.w * vv.w;
            }
            ctx[c] = acc;
        }
        __syncthreads();

        // ---- Phase P: u[s] = 10*tanh(ctx . KP[b,s] / sqrt(E)), KP streamed (L2) ----
        {
            float4 c4 = *(const float4*)&ctx[lane * 4];
#pragma unroll 1
            for (int r2 = 0; r2 < 25; r2++) {
                int s = w + 8 * r2;
                const float4* kp = (const float4*)&Pb[(size_t)s * PW + 256];
                float4 kv = kp[lane];
                float z = c4.x * kv.x + c4.y * kv.y + c4.z * kv.z + c4.w * kv.w;
#pragma unroll
                for (int o = 16; o; o >>= 1) z += __shfl_xor_sync(0xffffffffu, z, o);
                if (lane == 0) ush[s] = 10.f * tanhf(z * inv_scale);
            }
        }
        __syncthreads();

        // ---- Phase W+R: write raw logits, masked argmax (first-index ties) ----
        float myval = NEGF;
        {
            if (tid < SEQ) {
                float u = ush[tid];
                outLogits[((size_t)b * TSTEPS + t) * SEQ + tid] = u;
                if (!((maskw[tid >> 5] >> (tid & 31)) & 1u)) myval = u;
            }
            float val = myval; int vidx = tid;
#pragma unroll
            for (int o = 16; o; o >>= 1) {
                float ov = __shfl_xor_sync(0xffffffffu, val, o);
                int   oi = __shfl_xor_sync(0xffffffffu, vidx, o);
                if (ov > val || (ov == val && oi < vidx)) { val = ov; vidx = oi; }
            }
            if (lane == 0) { redv[w] = val; redi[w] = vidx; }
        }
        __syncthreads();
        if (tid == 0) {
            float bm = redv[0]; int bi = redi[0];
            for (int i = 1; i < 8; i++)
                if (redv[i] > bm) { bm = redv[i]; bi = redi[i]; }
            *s_bmax = bm; s_ints[2] = bi;
        }
        __syncthreads();
        {
            float e = expf(myval - *s_bmax);   // masked -> exp(-huge) = 0
#pragma unroll
            for (int o = 16; o; o >>= 1) e += __shfl_xor_sync(0xffffffffu, e, o);
            if (lane == 0) reds[w] = e;
        }
        __syncthreads();
        if (tid == 0) {
            float tot = 0.f;
            for (int i = 0; i < 8; i++) tot += reds[i];
            *s_logp += logf(tot);              // ce = logsumexp - max, max attained at idx
            int bi = s_ints[2];
            maskw[bi >> 5] |= (1u << (bi & 31));
            sols[t + 1] = bi;
            s_ints[0] = bi;
            if (t == 0) s_ints[1] = bi;
        }
        __syncthreads();
    }

    if (outLogp && tid == 0) outLogp[b] = *s_logp;
    if (outSol && tid < SEQ) outSol[b * SEQ + tid] = (float)sols[tid];
}

// -------------------------------- launcher --------------------------------------
extern "C" void kernel_launch(void* const* d_in, const int* in_sizes, int n_in,
                              void* d_out, int out_size) {
    const float* enc = (const float*)d_in[0];
    // d_in[1]=demands, d_in[2]=capacities : unused by the forward pass
    const float* vl = (const float*)d_in[3];
    const float* vf = (const float*)d_in[4];
    const float* Wq = (const float*)d_in[5];
    const float* Wk = (const float*)d_in[6];
    const float* Wv = (const float*)d_in[7];
    const float* Wo = (const float*)d_in[8];
    const float* Wp = (const float*)d_in[9];

    float* out = (float*)d_out;
    size_t L = (size_t)BATCH * TSTEPS * SEQ;   // 40,755,200 raw logits
    float* outLogp = nullptr;
    float* outSol  = nullptr;
    if ((size_t)out_size >= L + BATCH) outLogp = out + L;
    if ((size_t)out_size >= L + BATCH + (size_t)BATCH * SEQ) outSol = out + L + BATCH;

    const int gemm_smem   = (128 * 132 + 128 * 128) * 4;   // 133,120 B
    const int decode_smem = 54808 * 4;                     // 219,232 B
    cudaFuncSetAttribute(gemm_kernel,   cudaFuncAttributeMaxDynamicSharedMemorySize, gemm_smem);
    cudaFuncSetAttribute(decode_kernel, cudaFuncAttributeMaxDynamicSharedMemorySize, decode_smem);

    wcat_kernel<<<PW, 128>>>(Wk, Wv, Wo, Wp, Wq);
    prep_kernel<<<BATCH, 128>>>(enc, vl, vf, Wq);
    gemm_kernel<<<dim3(BATCH * SEQ / 128, PW / 128), 256, gemm_smem>>>(enc);
    decode_kernel<<<BATCH, 256, decode_smem>>>(out, outLogp, outSol);
}

// round 3
// speedup vs baseline: 2.8384x; 2.8384x over previous
#include <cuda_runtime.h>
#include <math.h>

#define BATCH 1024
#define SEQ   200
#define EMB   128
#define TSTEPS 199
#define PW    640      // P columns: [K(128) | V(128) | KP(128) | Q2(128) | Q3(128)]
#define KST   132      // K smem row stride (per s)
#define KPST  201      // KP-transposed smem row stride (per e), 201%32=9 coprime -> conflict-free
#define AST   204      // attn smem row stride (per head)
#define NEGF  (-3.402823466e38f)

// ---------------- device scratch ----------------
__device__ float g_P[(size_t)BATCH * SEQ * PW];   // precomputed projections
__device__ float g_Wcat[EMB * PW];
__device__ float g_qhat[BATCH * EMB];
__device__ float g_qvec[2 * EMB];

// ---------------- build combined weights: [Wk | Wv | Wp@Wo^T | Wq2 | Wq3] -------
__global__ void wcat_kernel(const float* __restrict__ Wk, const float* __restrict__ Wv,
                            const float* __restrict__ Wo, const float* __restrict__ Wp,
                            const float* __restrict__ Wq) {
    int e = threadIdx.x;
    int c = blockIdx.x;
    float v;
    if (c < 128) {
        v = Wk[e * 128 + c];
    } else if (c < 256) {
        v = Wv[e * 128 + (c - 128)];
    } else if (c < 384) {
        int i = c - 256;
        float s = 0.f;
        for (int j = 0; j < 128; j++) s += Wp[e * 128 + j] * Wo[i * 128 + j];
        v = s;
    } else if (c < 512) {
        v = Wq[(128 + e) * 128 + (c - 384)];
    } else {
        v = Wq[(256 + e) * 128 + (c - 512)];
    }
    g_Wcat[e * PW + c] = v;
}

// ---------------- h_hat mean + qhat = h_hat @ Wq1 (+ vl/vf projections) ---------
__global__ void prep_kernel(const float* __restrict__ enc, const float* __restrict__ vl,
                            const float* __restrict__ vf, const float* __restrict__ Wq) {
    __shared__ float hh[EMB];
    int b = blockIdx.x, e = threadIdx.x;
    const float* p = enc + (size_t)b * SEQ * EMB + e;
    float s = 0.f;
    for (int i = 0; i < SEQ; i++) s += p[(size_t)i * EMB];
    hh[e] = s * (1.0f / (float)SEQ);
    __syncthreads();
    float q = 0.f;
    for (int k = 0; k < 128; k++) q += hh[k] * Wq[k * 128 + e];
    g_qhat[b * EMB + e] = q;
    if (b == 0) {
        float a = 0.f, c = 0.f;
        for (int k = 0; k < 128; k++) {
            a += vl[k] * Wq[(128 + k) * 128 + e];
            c += vf[k] * Wq[(256 + k) * 128 + e];
        }
        g_qvec[e] = a;
        g_qvec[128 + e] = c;
    }
}

// ---------------- SGEMM: g_P[204800,640] = enc[204800,128] @ g_Wcat[128,640] ----
__global__ __launch_bounds__(256, 1) void gemm_kernel(const float* __restrict__ A) {
    extern __shared__ float smg[];
    float* As = smg;               // As[k*132 + m]
    float* Bs = smg + 128 * 132;   // Bs[k*128 + n]
    int m0 = blockIdx.x * 128, n0 = blockIdx.y * 128;
    int tid = threadIdx.x;
    for (int it = 0; it < 64; it++) {
        int idx = tid + it * 256;
        int k = idx & 127, m = idx >> 7;
        As[k * 132 + m] = A[(size_t)(m0 + m) * 128 + k];
        Bs[m * 128 + k] = g_Wcat[m * PW + n0 + k];
    }
    __syncthreads();
    int tx = tid & 15, ty = tid >> 4;
    float acc[8][8];
#pragma unroll
    for (int i = 0; i < 8; i++)
#pragma unroll
        for (int j = 0; j < 8; j++) acc[i][j] = 0.f;
#pragma unroll 4
    for (int k = 0; k < 128; k++) {
        float4 a0 = *(float4*)&As[k * 132 + ty * 8];
        float4 a1 = *(float4*)&As[k * 132 + ty * 8 + 4];
        float4 b0 = *(float4*)&Bs[k * 128 + tx * 8];
        float4 b1 = *(float4*)&Bs[k * 128 + tx * 8 + 4];
        float av[8] = {a0.x, a0.y, a0.z, a0.w, a1.x, a1.y, a1.z, a1.w};
        float bv[8] = {b0.x, b0.y, b0.z, b0.w, b1.x, b1.y, b1.z, b1.w};
#pragma unroll
        for (int i = 0; i < 8; i++)
#pragma unroll
            for (int j = 0; j < 8; j++) acc[i][j] += av[i] * bv[j];
    }
#pragma unroll
    for (int i = 0; i < 8; i++) {
        float* cr = &g_P[(size_t)(m0 + ty * 8 + i) * PW + n0 + tx * 8];
        *(float4*)cr       = make_float4(acc[i][0], acc[i][1], acc[i][2], acc[i][3]);
        *(float4*)(cr + 4) = make_float4(acc[i][4], acc[i][5], acc[i][6], acc[i][7]);
    }
}

// ---------------- persistent per-batch greedy decode (199 steps) ----------------
__global__ __launch_bounds__(256, 1) void decode_kernel(float* __restrict__ outLogits,
                                                        float* __restrict__ outLogp,
                                                        float* __restrict__ outSol) {
    extern __shared__ float sm[];
    float*    Ksh    = sm;                       // 200*132
    float*    KPt    = Ksh + SEQ * KST;          // 128*201 (KP transposed: KPt[e*KPST+s])
    float*    attn   = KPt + EMB * KPST;         // 8*204
    float*    ctxp   = attn + 8 * AST;           // 8*128 partial ctx per warp
    float*    qv     = ctxp + 8 * 128;           // 128
    float*    ctx    = qv + EMB;                 // 128
    float*    redv   = ctx + EMB;                // 8
    float*    reds   = redv + 8;                 // 8
    int*      redi   = (int*)(reds + 8);         // 8
    unsigned* maskw  = (unsigned*)(redi + 8);    // 8
    int*      sols   = (int*)(maskw + 8);        // 200
    float*    s_logp = (float*)(sols + SEQ);
    float*    s_bmax = s_logp + 1;
    int*      s_bi   = (int*)(s_bmax + 1);

    int tid = threadIdx.x, lane = tid & 31, w = tid >> 5;
    int b = blockIdx.x;
    const float* __restrict__ Pb = g_P + (size_t)b * SEQ * PW;

    // ---- one-time SMEM loads: K (row-major padded) and KP (transposed) ----
    for (int i = tid; i < SEQ * EMB; i += 256) {
        int s = i >> 7, e = i & 127;
        Ksh[s * KST + e] = Pb[(size_t)s * PW + e];
    }
    for (int i = tid; i < SEQ * EMB; i += 256) {
        int s = i >> 7, e = i & 127;
        KPt[e * KPST + s] = Pb[(size_t)s * PW + 256 + e];
    }

    float qhat_r = 0.f, q2r = 0.f, q3r = 0.f;
    if (tid < 128) {
        qhat_r = g_qhat[b * EMB + tid];
        q2r = g_qvec[tid];          // t=0: last = vl
        q3r = g_qvec[128 + tid];    // t=0: first = vf
    }
    if (tid < 8) maskw[tid] = (tid == 0) ? 1u : 0u;
    if (tid == 0) { *s_logp = 0.f; sols[0] = 0; }
    __syncthreads();

    const float inv_scale = 0.08838834764831845f;   // 1/sqrt(128)

    for (int t = 0; t < TSTEPS; t++) {
        // ---- [1] accumulate previous CE + build q (pre-scaled by 1/sqrt(dh)) ----
        if (tid == 0 && t > 0) {
            float tot = 0.f;
#pragma unroll
            for (int i = 0; i < 8; i++) tot += reds[i];
            *s_logp += logf(tot);
        }
        if (tid < 128) qv[tid] = (qhat_r + q2r + q3r) * 0.25f;
        __syncthreads();

        // ---- [2] masked scores + softmax: warp w = head ----
        {
            const float4* qp = (const float4*)&qv[w << 4];
            float4 q0 = qp[0], q1 = qp[1], q2 = qp[2], q3 = qp[3];
            float sc[7];
#pragma unroll
            for (int r = 0; r < 7; r++) {
                int s = lane + (r << 5);
                float v = NEGF;
                if (s < SEQ && !((maskw[s >> 5] >> (s & 31)) & 1u)) {
                    const float4* kr = (const float4*)&Ksh[s * KST + (w << 4)];
                    float4 k0 = kr[0], k1 = kr[1], k2 = kr[2], k3 = kr[3];
                    v  = q0.x * k0.x + q0.y * k0.y + q0.z * k0.z + q0.w * k0.w;
                    v += q1.x * k1.x + q1.y * k1.y + q1.z * k1.z + q1.w * k1.w;
                    v += q2.x * k2.x + q2.y * k2.y + q2.z * k2.z + q2.w * k2.w;
                    v += q3.x * k3.x + q3.y * k3.y + q3.z * k3.z + q3.w * k3.w;
                }
                sc[r] = v;
            }
            float mx = sc[0];
#pragma unroll
            for (int r = 1; r < 7; r++) mx = fmaxf(mx, sc[r]);
#pragma unroll
            for (int o = 16; o; o >>= 1) mx = fmaxf(mx, __shfl_xor_sync(0xffffffffu, mx, o));
            float er[7], ssum = 0.f;
#pragma unroll
            for (int r = 0; r < 7; r++) { er[r] = expf(sc[r] - mx); ssum += er[r]; }
#pragma unroll
            for (int o = 16; o; o >>= 1) ssum += __shfl_xor_sync(0xffffffffu, ssum, o);
            float inv = 1.f / ssum;
#pragma unroll
            for (int r = 0; r < 7; r++) {
                int s = lane + (r << 5);
                if (s < SEQ) attn[w * AST + s] = er[r] * inv;
            }
        }
        __syncthreads();

        // ---- [3] ctx partials: warp w handles s in [25w, 25w+25), V streamed (L2) ----
        {
            float a0 = 0.f, a1 = 0.f, a2 = 0.f, a3 = 0.f;
            const float* arow = &attn[(lane >> 2) * AST];
            const float* vbase = Pb + 128 + (lane << 2);
            int s0 = w * 25;
#pragma unroll
            for (int i = 0; i < 25; i++) {
                int s = s0 + i;
                float4 vv = *(const float4*)(vbase + (size_t)s * PW);
                float a = arow[s];
                a0 += a * vv.x; a1 += a * vv.y; a2 += a * vv.z; a3 += a * vv.w;
            }
            float* cp = &ctxp[w * 128 + (lane << 2)];
            cp[0] = a0; cp[1] = a1; cp[2] = a2; cp[3] = a3;
        }
        __syncthreads();

        // ---- [4] ctx tree-combine ----
        if (tid < 128) {
            float s = 0.f;
#pragma unroll
            for (int i = 0; i < 8; i++) s += ctxp[i * 128 + tid];
            ctx[tid] = s;
        }
        __syncthreads();

        // ---- [5] pointer logits (thread-per-s from SMEM) + warp argmax ----
        float myval = NEGF;
        if (tid < SEQ) {
            float z0 = 0.f, z1 = 0.f, z2 = 0.f, z3 = 0.f;
#pragma unroll
            for (int e4 = 0; e4 < 32; e4++) {
                float4 c4 = *(const float4*)&ctx[e4 << 2];
                const float* kp = &KPt[(e4 << 2) * KPST + tid];
                z0 += c4.x * kp[0];
                z1 += c4.y * kp[KPST];
                z2 += c4.z * kp[2 * KPST];
                z3 += c4.w * kp[3 * KPST];
            }
            float z = (z0 + z1) + (z2 + z3);
            float u = 10.f * tanhf(z * inv_scale);
            outLogits[((size_t)b * TSTEPS + t) * SEQ + tid] = u;
            if (!((maskw[tid >> 5] >> (tid & 31)) & 1u)) myval = u;
        }
        {
            float val = myval; int vidx = tid;
#pragma unroll
            for (int o = 16; o; o >>= 1) {
                float ov = __shfl_xor_sync(0xffffffffu, val, o);
                int   oi = __shfl_xor_sync(0xffffffffu, vidx, o);
                if (ov > val || (ov == val && oi < vidx)) { val = ov; vidx = oi; }
            }
            if (lane == 0) { redv[w] = val; redi[w] = vidx; }
        }
        __syncthreads();

        // ---- [6] argmax finalize + mask/sol update ----
        if (tid == 0) {
            float bm = redv[0]; int bi = redi[0];
#pragma unroll
            for (int i = 1; i < 8; i++)
                if (redv[i] > bm) { bm = redv[i]; bi = redi[i]; }
            *s_bmax = bm; *s_bi = bi;
            maskw[bi >> 5] |= (1u << (bi & 31));
            sols[t + 1] = bi;
        }
        __syncthreads();

        // ---- [7] CE exp-sum + prefetch next-step q rows (hides L2 latency) ----
        {
            float e = expf(myval - *s_bmax);   // masked lanes -> 0
#pragma unroll
            for (int o = 16; o; o >>= 1) e += __shfl_xor_sync(0xffffffffu, e, o);
            if (lane == 0) reds[w] = e;
        }
        if (tid < 128) {
            int bi = *s_bi;
            q2r = Pb[(size_t)bi * PW + 384 + tid];           // Q2[b, idx]
            if (t == 0) q3r = Pb[(size_t)bi * PW + 512 + tid]; // Q3[b, idx0] (constant after)
        }
        __syncthreads();
    }

    if (tid == 0 && outLogp) {
        float tot = 0.f;
        for (int i = 0; i < 8; i++) tot += reds[i];
        outLogp[b] = *s_logp + logf(tot);
    }
    if (outSol && tid < SEQ) outSol[b * SEQ + tid] = (float)sols[tid];
}

// -------------------------------- launcher --------------------------------------
extern "C" void kernel_launch(void* const* d_in, const int* in_sizes, int n_in,
                              void* d_out, int out_size) {
    const float* enc = (const float*)d_in[0];
    const float* vl = (const float*)d_in[3];
    const float* vf = (const float*)d_in[4];
    const float* Wq = (const float*)d_in[5];
    const float* Wk = (const float*)d_in[6];
    const float* Wv = (const float*)d_in[7];
    const float* Wo = (const float*)d_in[8];
    const float* Wp = (const float*)d_in[9];

    float* out = (float*)d_out;
    size_t L = (size_t)BATCH * TSTEPS * SEQ;
    float* outLogp = nullptr;
    float* outSol  = nullptr;
    if ((size_t)out_size >= L + BATCH) outLogp = out + L;
    if ((size_t)out_size >= L + BATCH + (size_t)BATCH * SEQ) outSol = out + L + BATCH;

    const int gemm_smem   = (128 * 132 + 128 * 128) * 4;   // 133,120 B
    const int decode_smem = 55280 * 4;                     // 221,120 B
    cudaFuncSetAttribute(gemm_kernel,   cudaFuncAttributeMaxDynamicSharedMemorySize, gemm_smem);
    cudaFuncSetAttribute(decode_kernel, cudaFuncAttributeMaxDynamicSharedMemorySize, decode_smem);

    wcat_kernel<<<PW, 128>>>(Wk, Wv, Wo, Wp, Wq);
    prep_kernel<<<BATCH, 128>>>(enc, vl, vf, Wq);
    gemm_kernel<<<dim3(BATCH * SEQ / 128, PW / 128), 256, gemm_smem>>>(enc);
    decode_kernel<<<BATCH, 256, decode_smem>>>(out, outLogp, outSol);
}

// round 4
// speedup vs baseline: 3.2140x; 1.1323x over previous
#include <cuda_runtime.h>
#include <math.h>

#define BATCH 1024
#define SEQ   200
#define EMB   128
#define TSTEPS 199
#define PW    640      // P columns: [K(128) | V(128) | KP(128) | Q2(128) | Q3(128)]
#define VST   132      // V smem row stride (per s)
#define KPST  201      // KP-transposed row stride
#define AST   204      // attn smem row stride (per head) -> h*204%32 distinct banks
#define NEGF  (-3.402823466e38f)

// ---------------- device scratch ----------------
__device__ float g_P[(size_t)BATCH * SEQ * PW];
__device__ float g_Wcat[EMB * PW];
__device__ float g_qhat[BATCH * EMB];
__device__ float g_qvec[2 * EMB];

// ---------------- build combined weights: [Wk | Wv | Wp@Wo^T | Wq2 | Wq3] -------
__global__ void wcat_kernel(const float* __restrict__ Wk, const float* __restrict__ Wv,
                            const float* __restrict__ Wo, const float* __restrict__ Wp,
                            const float* __restrict__ Wq) {
    int e = threadIdx.x;
    int c = blockIdx.x;
    float v;
    if (c < 128) {
        v = Wk[e * 128 + c];
    } else if (c < 256) {
        v = Wv[e * 128 + (c - 128)];
    } else if (c < 384) {
        int i = c - 256;
        float s = 0.f;
        for (int j = 0; j < 128; j++) s += Wp[e * 128 + j] * Wo[i * 128 + j];
        v = s;
    } else if (c < 512) {
        v = Wq[(128 + e) * 128 + (c - 384)];
    } else {
        v = Wq[(256 + e) * 128 + (c - 512)];
    }
    g_Wcat[e * PW + c] = v;
}

// ---------------- h_hat mean + qhat = h_hat @ Wq1 (+ vl/vf projections) ---------
__global__ void prep_kernel(const float* __restrict__ enc, const float* __restrict__ vl,
                            const float* __restrict__ vf, const float* __restrict__ Wq) {
    __shared__ float hh[EMB];
    int b = blockIdx.x, e = threadIdx.x;
    const float* p = enc + (size_t)b * SEQ * EMB + e;
    float s = 0.f;
    for (int i = 0; i < SEQ; i++) s += p[(size_t)i * EMB];
    hh[e] = s * (1.0f / (float)SEQ);
    __syncthreads();
    float q = 0.f;
    for (int k = 0; k < 128; k++) q += hh[k] * Wq[k * 128 + e];
    g_qhat[b * EMB + e] = q;
    if (b == 0) {
        float a = 0.f, c = 0.f;
        for (int k = 0; k < 128; k++) {
            a += vl[k] * Wq[(128 + k) * 128 + e];
            c += vf[k] * Wq[(256 + k) * 128 + e];
        }
        g_qvec[e] = a;
        g_qvec[128 + e] = c;
    }
}

// ---------------- SGEMM: g_P[204800,640] = enc[204800,128] @ g_Wcat[128,640] ----
__global__ __launch_bounds__(512, 1) void gemm_kernel(const float* __restrict__ A) {
    extern __shared__ float smg[];
    float* As = smg;               // As[k*132 + m]
    float* Bs = smg + 128 * 132;   // Bs[k*128 + n]
    int m0 = blockIdx.x * 128, n0 = blockIdx.y * 128;
    int tid = threadIdx.x;
#pragma unroll
    for (int it = 0; it < 32; it++) {
        int idx = tid + it * 512;
        int k = idx & 127, m = idx >> 7;
        As[k * 132 + m] = A[(size_t)(m0 + m) * 128 + k];
        Bs[m * 128 + k] = g_Wcat[m * PW + n0 + k];   // m = k-dim, k = n-dim
    }
    __syncthreads();
    int tx = tid & 31, ty = tid >> 5;   // 32 x 16 threads -> 4-col x 8-row microtile
    float acc[8][4];
#pragma unroll
    for (int i = 0; i < 8; i++)
#pragma unroll
        for (int j = 0; j < 4; j++) acc[i][j] = 0.f;
#pragma unroll 4
    for (int k = 0; k < 128; k++) {
        float4 a0 = *(float4*)&As[k * 132 + ty * 8];
        float4 a1 = *(float4*)&As[k * 132 + ty * 8 + 4];
        float4 b  = *(float4*)&Bs[k * 128 + tx * 4];
        float av[8] = {a0.x, a0.y, a0.z, a0.w, a1.x, a1.y, a1.z, a1.w};
#pragma unroll
        for (int i = 0; i < 8; i++) {
            acc[i][0] += av[i] * b.x;
            acc[i][1] += av[i] * b.y;
            acc[i][2] += av[i] * b.z;
            acc[i][3] += av[i] * b.w;
        }
    }
#pragma unroll
    for (int i = 0; i < 8; i++) {
        float* cr = &g_P[(size_t)(m0 + ty * 8 + i) * PW + n0 + tx * 4];
        *(float4*)cr = make_float4(acc[i][0], acc[i][1], acc[i][2], acc[i][3]);
    }
}

// ---------------- persistent per-batch greedy decode (199 steps, 512 thr) -------
__global__ __launch_bounds__(512, 1) void decode_kernel(float* __restrict__ outLogits,
                                                        float* __restrict__ outLogp,
                                                        float* __restrict__ outSol) {
    extern __shared__ float sm[];
    float*    Vsm   = sm;                          // 200*132 = 26400
    float*    KPt   = Vsm + SEQ * VST;             // 128*201+32 = 25760 (split-padded)
    float*    attn  = KPt + 128 * KPST + 32;       // 8*204
    float*    ctxp  = attn + 8 * AST;              // 16*128
    float*    qv    = ctxp + 16 * 128;             // 128
    float*    ctx   = qv + EMB;                    // 128
    float*    wmax  = ctx + EMB;                   // 16
    float*    wsum  = wmax + 16;                   // 16
    float*    redv  = wsum + 16;                   // 16
    int*      redi  = (int*)(redv + 16);           // 16
    float*    reds  = (float*)(redi + 16);         // 16
    unsigned* maskw = (unsigned*)(reds + 16);      // 8
    int*      sols  = (int*)(maskw + 8);           // 200
    float*    s_logp = (float*)(sols + SEQ);
    float*    s_bmax = s_logp + 1;
    int*      s_bi   = (int*)(s_bmax + 1);

    int tid = threadIdx.x, lane = tid & 31, w = tid >> 5;
    int b = blockIdx.x;
    const float* __restrict__ Pb = g_P + (size_t)b * SEQ * PW;

    // ---- one-time SMEM loads: V (row-major padded) and KP (transposed, split-pad) ----
    for (int i = tid; i < SEQ * EMB; i += 512) {
        int s = i >> 7, e = i & 127;
        Vsm[s * VST + e] = Pb[(size_t)s * PW + 128 + e];
    }
    for (int i = tid; i < SEQ * EMB; i += 512) {
        int s = i >> 7, e = i & 127;
        KPt[e * KPST + (e >= 64 ? 16 : 0) + s] = Pb[(size_t)s * PW + 256 + e];
    }

    // ---- K slice in registers: warp w = (head h, sub), rows r=0..3: s = sub*128+32r+lane
    int h = w >> 1, sub = w & 1;
    float4 kreg[4][4];
#pragma unroll
    for (int r = 0; r < 4; r++) {
        int s = sub * 128 + (r << 5) + lane;
        if (s < SEQ) {
            const float4* kp = (const float4*)&Pb[(size_t)s * PW + (h << 4)];
            kreg[r][0] = kp[0]; kreg[r][1] = kp[1]; kreg[r][2] = kp[2]; kreg[r][3] = kp[3];
        } else {
            kreg[r][0] = kreg[r][1] = kreg[r][2] = kreg[r][3] = make_float4(0.f, 0.f, 0.f, 0.f);
        }
    }

    float qhat_r = 0.f, q2r = 0.f, q3r = 0.f;
    if (tid < 128) {
        qhat_r = g_qhat[b * EMB + tid];
        q2r = g_qvec[tid];          // t=0: last = vl
        q3r = g_qvec[128 + tid];    // t=0: first = vf
    }
    if (tid < 8) maskw[tid] = (tid == 0) ? 1u : 0u;
    if (tid == 0) { *s_logp = 0.f; sols[0] = 0; }
    __syncthreads();

    const float inv_scale = 0.08838834764831845f;   // 1/sqrt(128)

    for (int t = 0; t < TSTEPS; t++) {
        // ---- [1] accumulate previous CE + build q (pre-scaled by 1/sqrt(dh)) ----
        if (tid == 0 && t > 0) {
            float tot = 0.f;
#pragma unroll
            for (int i = 0; i < 13; i++) tot += reds[i];
            *s_logp += logf(tot);
        }
        if (tid < 128) qv[tid] = (qhat_r + q2r + q3r) * 0.25f;
        __syncthreads();

        // ---- [2a] scores from register K, per-warp max ----
        float sc[4];
        {
            const float4* qp = (const float4*)&qv[h << 4];
            float4 q0 = qp[0], q1 = qp[1], q2 = qp[2], q3 = qp[3];
#pragma unroll
            for (int r = 0; r < 4; r++) {
                int s = sub * 128 + (r << 5) + lane;
                float v;
                v  = q0.x * kreg[r][0].x + q0.y * kreg[r][0].y + q0.z * kreg[r][0].z + q0.w * kreg[r][0].w;
                v += q1.x * kreg[r][1].x + q1.y * kreg[r][1].y + q1.z * kreg[r][1].z + q1.w * kreg[r][1].w;
                v += q2.x * kreg[r][2].x + q2.y * kreg[r][2].y + q2.z * kreg[r][2].z + q2.w * kreg[r][2].w;
                v += q3.x * kreg[r][3].x + q3.y * kreg[r][3].y + q3.z * kreg[r][3].z + q3.w * kreg[r][3].w;
                bool ok = (s < SEQ) && !((maskw[4 * sub + r] >> lane) & 1u);
                sc[r] = ok ? v : NEGF;
            }
            float mx = fmaxf(fmaxf(sc[0], sc[1]), fmaxf(sc[2], sc[3]));
#pragma unroll
            for (int o = 16; o; o >>= 1) mx = fmaxf(mx, __shfl_xor_sync(0xffffffffu, mx, o));
            if (lane == 0) wmax[w] = mx;
        }
        __syncthreads();

        // ---- [2b] exp (head max), store unnormalized attn, per-warp sum ----
        {
            float mx = fmaxf(wmax[2 * h], wmax[2 * h + 1]);
            float ssum = 0.f;
#pragma unroll
            for (int r = 0; r < 4; r++) {
                int s = sub * 128 + (r << 5) + lane;
                float er = expf(sc[r] - mx);      // NEGF -> 0
                ssum += er;
                if (s < SEQ) attn[h * AST + s] = er;
            }
#pragma unroll
            for (int o = 16; o; o >>= 1) ssum += __shfl_xor_sync(0xffffffffu, ssum, o);
            if (lane == 0) wsum[w] = ssum;
        }
        __syncthreads();

        // ---- [3] ctx partials (16 warps x 12/13 s, V from SMEM, attn unnormalized) ----
        {
            int s0, cnt;
            if (w < 8) { s0 = w * 13; cnt = 13; } else { s0 = 104 + (w - 8) * 12; cnt = 12; }
            int hh = lane >> 2;
            const float* arow = &attn[hh * AST];
            float a0 = 0.f, a1 = 0.f, a2 = 0.f, a3 = 0.f;
#pragma unroll
            for (int i = 0; i < 13; i++) {
                if (i < cnt) {
                    int s = s0 + i;
                    float a = arow[s];
                    float4 vv = *(const float4*)&Vsm[s * VST + (lane << 2)];
                    a0 += a * vv.x; a1 += a * vv.y; a2 += a * vv.z; a3 += a * vv.w;
                }
            }
            *(float4*)&ctxp[w * 128 + (lane << 2)] = make_float4(a0, a1, a2, a3);
        }
        __syncthreads();

        // ---- [4] ctx combine + softmax normalization ----
        if (tid < 128) {
            float s = 0.f;
#pragma unroll
            for (int i = 0; i < 16; i++) s += ctxp[i * 128 + tid];
            int hd = tid >> 4;
            float inv = 1.f / (wsum[2 * hd] + wsum[2 * hd + 1]);
            ctx[tid] = s * inv;
        }
        __syncthreads();

        // ---- [5] pointer logits: 13 warps x 16 s x 2 e-halves, KPt smem ----
        float myval = NEGF;
        int myidx = tid;   // default; overwritten below for phase-5 warps
        if (w < 13) {
            int sl = lane & 15, half = lane >> 4;
            int s = (w << 4) + sl;
            const float* kp = &KPt[half * (64 * KPST + 16) + s];
            float z0 = 0.f, z1 = 0.f, z2 = 0.f, z3 = 0.f;
#pragma unroll
            for (int j = 0; j < 16; j++) {
                float4 c4 = *(const float4*)&ctx[(half << 6) + (j << 2)];
                z0 += c4.x * kp[(4 * j + 0) * KPST];
                z1 += c4.y * kp[(4 * j + 1) * KPST];
                z2 += c4.z * kp[(4 * j + 2) * KPST];
                z3 += c4.w * kp[(4 * j + 3) * KPST];
            }
            float z = (z0 + z1) + (z2 + z3);
            z += __shfl_xor_sync(0xffffffffu, z, 16);
            float u = 10.f * tanhf(z * inv_scale);
            myidx = s;
            if (half == 0 && s < SEQ) {
                outLogits[((size_t)b * TSTEPS + t) * SEQ + s] = u;
                if (!((maskw[s >> 5] >> (s & 31)) & 1u)) myval = u;
            }
            float val = myval; int vidx = myidx;
#pragma unroll
            for (int o = 16; o; o >>= 1) {
                float ov = __shfl_xor_sync(0xffffffffu, val, o);
                int   oi = __shfl_xor_sync(0xffffffffu, vidx, o);
                if (ov > val || (ov == val && oi < vidx)) { val = ov; vidx = oi; }
            }
            if (lane == 0) { redv[w] = val; redi[w] = vidx; }
        }
        __syncthreads();

        // ---- [6] argmax finalize + mask/sol update ----
        if (tid == 0) {
            float bm = redv[0]; int bi = redi[0];
#pragma unroll
            for (int i = 1; i < 13; i++)
                if (redv[i] > bm) { bm = redv[i]; bi = redi[i]; }
            *s_bmax = bm; *s_bi = bi;
            maskw[bi >> 5] |= (1u << (bi & 31));
            sols[t + 1] = bi;
        }
        __syncthreads();

        // ---- [7] CE exp-sums + prefetch next-step q rows ----
        if (w < 13) {
            float e = expf(myval - *s_bmax);   // masked / invalid lanes -> 0
#pragma unroll
            for (int o = 16; o; o >>= 1) e += __shfl_xor_sync(0xffffffffu, e, o);
            if (lane == 0) reds[w] = e;
        }
        if (tid < 128) {
            int bi = *s_bi;
            q2r = Pb[(size_t)bi * PW + 384 + tid];             // Q2[b, idx]
            if (t == 0) q3r = Pb[(size_t)bi * PW + 512 + tid]; // Q3[b, idx0]
        }
        __syncthreads();
    }

    if (tid == 0 && outLogp) {
        float tot = 0.f;
        for (int i = 0; i < 13; i++) tot += reds[i];
        outLogp[b] = *s_logp + logf(tot);
    }
    if (outSol && tid < SEQ) outSol[b * SEQ + tid] = (float)sols[tid];
}

// -------------------------------- launcher --------------------------------------
extern "C" void kernel_launch(void* const* d_in, const int* in_sizes, int n_in,
                              void* d_out, int out_size) {
    const float* enc = (const float*)d_in[0];
    const float* vl = (const float*)d_in[3];
    const float* vf = (const float*)d_in[4];
    const float* Wq = (const float*)d_in[5];
    const float* Wk = (const float*)d_in[6];
    const float* Wv = (const float*)d_in[7];
    const float* Wo = (const float*)d_in[8];
    const float* Wp = (const float*)d_in[9];

    float* out = (float*)d_out;
    size_t L = (size_t)BATCH * TSTEPS * SEQ;
    float* outLogp = nullptr;
    float* outSol  = nullptr;
    if ((size_t)out_size >= L + BATCH) outLogp = out + L;
    if ((size_t)out_size >= L + BATCH + (size_t)BATCH * SEQ) outSol = out + L + BATCH;

    const int gemm_smem   = (128 * 132 + 128 * 128) * 4;   // 133,120 B
    // V 26400 + KPt 25792 + attn 1632 + ctxp 2048 + qv/ctx 256 + red/misc ~300 floats
    const int decode_smem = (26400 + 25792 + 1632 + 2048 + 128 + 128 + 16 + 16 + 16 + 16 + 16 + 8 + 200 + 8) * 4;
    cudaFuncSetAttribute(gemm_kernel,   cudaFuncAttributeMaxDynamicSharedMemorySize, gemm_smem);
    cudaFuncSetAttribute(decode_kernel, cudaFuncAttributeMaxDynamicSharedMemorySize, decode_smem);

    wcat_kernel<<<PW, 128>>>(Wk, Wv, Wo, Wp, Wq);
    prep_kernel<<<BATCH, 128>>>(enc, vl, vf, Wq);
    gemm_kernel<<<dim3(BATCH * SEQ / 128, PW / 128), 512, gemm_smem>>>(enc);
    decode_kernel<<<BATCH, 512, decode_smem>>>(out, outLogp, outSol);
}